// round 3
// baseline (speedup 1.0000x reference)
#include <cuda_runtime.h>
#include <cstdint>

// ---------------------------------------------------------------------------
// starConvexLoss
//   logp = log_softmax(pred)                        [B,C]
//   wstar = -mean_b logp[b, t_b]
//   per s:  w  = -(1/B) sum_b  sum_c softmax(n+oh)      * logp
//           wt = -(1/B) sum_b  sum_c softmax(0.5n+oh)   * logp
//           n2 = sum_{b,c} n^2
//   sc1 = max(wstar-wt,0); sc2 = max(wstar-w+0.05*n2,0)
//   sc3 = max(wt-0.5wstar+0.5w+0.0125*n2,0)
//   out = wstar + 0.05 * sum_s (sc1+sc2+sc3)
// ---------------------------------------------------------------------------

#define C_DIM 10
#define BPS   32          // blocks per s in stage 2
#define TPB   256

static __device__ float g_logp[65536 * C_DIM];   // 2.6 MB, L2-resident
static __device__ float g_Sw[256];
static __device__ float g_Swt[256];
static __device__ float g_Sn2[256];
static __device__ float g_wstar;

// ---- fast math helpers ----------------------------------------------------
__device__ __forceinline__ float ex2a(float x) {
    float r; asm("ex2.approx.f32 %0, %1;" : "=f"(r) : "f"(x)); return r;
}
__device__ __forceinline__ float lg2a(float x) {
    float r; asm("lg2.approx.f32 %0, %1;" : "=f"(r) : "f"(x)); return r;
}
__device__ __forceinline__ float rcpa(float x) {
    float r; asm("rcp.approx.f32 %0, %1;" : "=f"(r) : "f"(x)); return r;
}

// ---- packed f32x2 (Blackwell; ptxas never auto-fuses these) ---------------
typedef unsigned long long u64;
__device__ __forceinline__ u64 fma2(u64 a, u64 b, u64 c) {
    u64 d; asm("fma.rn.f32x2 %0, %1, %2, %3;" : "=l"(d) : "l"(a), "l"(b), "l"(c)); return d;
}
__device__ __forceinline__ u64 add2(u64 a, u64 b) {
    u64 d; asm("add.rn.f32x2 %0, %1, %2;" : "=l"(d) : "l"(a), "l"(b)); return d;
}
__device__ __forceinline__ u64 mul2(u64 a, u64 b) {
    u64 d; asm("mul.rn.f32x2 %0, %1, %2;" : "=l"(d) : "l"(a), "l"(b)); return d;
}
__device__ __forceinline__ u64 pk(float x, float y) {
    u64 d; asm("mov.b64 %0, {%1, %2};" : "=l"(d) : "f"(x), "f"(y)); return d;
}
__device__ __forceinline__ float2 upk(u64 v) {
    float2 f; asm("mov.b64 {%0, %1}, %2;" : "=f"(f.x), "=f"(f.y) : "l"(v)); return f;
}

// ---- constants --------------------------------------------------------------
#define KH   0.7213475204444817f     // 0.5 * log2(e)
#define L2E  1.4426950408889634f
#define LN2  0.6931471805599453f
#define EM1  1.7182818284590452f     // e - 1

// ---- block reduction --------------------------------------------------------
__device__ __forceinline__ void reduce3(float& a, float& b, float& c) {
    #pragma unroll
    for (int o = 16; o; o >>= 1) {
        a += __shfl_xor_sync(0xffffffffu, a, o);
        b += __shfl_xor_sync(0xffffffffu, b, o);
        c += __shfl_xor_sync(0xffffffffu, c, o);
    }
}

// ---- stage 0: zero accumulators --------------------------------------------
__global__ void k_init() {
    int i = threadIdx.x;
    if (i < 256) { g_Sw[i] = 0.f; g_Swt[i] = 0.f; g_Sn2[i] = 0.f; }
    if (i == 0) g_wstar = 0.f;
}

// ---- stage 1: log-softmax + wstar partials ----------------------------------
__global__ void __launch_bounds__(TPB) k_logsoftmax(
    const float* __restrict__ pred, const int* __restrict__ targets, int B) {
    int b = blockIdx.x * blockDim.x + threadIdx.x;
    float part = 0.f;
    if (b < B) {
        const float2* pr = (const float2*)pred + (size_t)b * (C_DIM / 2);
        float p[C_DIM];
        #pragma unroll
        for (int k = 0; k < C_DIM / 2; k++) {
            float2 v = pr[k]; p[2 * k] = v.x; p[2 * k + 1] = v.y;
        }
        float m = p[0];
        #pragma unroll
        for (int c = 1; c < C_DIM; c++) m = fmaxf(m, p[c]);
        float sum = 0.f;
        #pragma unroll
        for (int c = 0; c < C_DIM; c++) sum += ex2a((p[c] - m) * L2E);
        float lse = fmaf(lg2a(sum), LN2, m);
        float2* outp = (float2*)g_logp + (size_t)b * (C_DIM / 2);
        #pragma unroll
        for (int k = 0; k < C_DIM / 2; k++)
            outp[k] = make_float2(p[2 * k] - lse, p[2 * k + 1] - lse);
        int t = targets[b];
        part = lse - p[t];               // -logp[b,t]
    }
    // block reduce
    #pragma unroll
    for (int o = 16; o; o >>= 1) part += __shfl_xor_sync(0xffffffffu, part, o);
    __shared__ float sm[TPB / 32];
    int lane = threadIdx.x & 31, w = threadIdx.x >> 5;
    if (lane == 0) sm[w] = part;
    __syncthreads();
    if (w == 0) {
        float v = (lane < TPB / 32) ? sm[lane] : 0.f;
        #pragma unroll
        for (int o = 4; o; o >>= 1) v += __shfl_xor_sync(0xffffffffu, v, o);
        if (lane == 0) atomicAdd(&g_wstar, v);
    }
}

// ---- stage 2: the big one ----------------------------------------------------
__global__ void __launch_bounds__(TPB) k_main(
    const float* __restrict__ noise, const int* __restrict__ targets,
    int B, int rowsPerBlock) {
    int s   = blockIdx.x / BPS;
    int blk = blockIdx.x % BPS;
    int b0 = blk * rowsPerBlock;
    int bend = min(b0 + rowsPerBlock, B);

    float wacc = 0.f, wtacc = 0.f;
    u64 n2p = 0ull;                                   // packed (0.f, 0.f)

    const u64* nbase = (const u64*)noise;
    const u64* lbase = (const u64*)g_logp;

    for (int b = b0 + threadIdx.x; b < bend; b += TPB) {
        const u64* nr = nbase + ((size_t)s * B + b) * (C_DIM / 2);
        const u64* lr = lbase + (size_t)b * (C_DIM / 2);
        u64 sep = 0ull, dotp = 0ull, selp = 0ull, dotlp = 0ull;
        #pragma unroll
        for (int k = 0; k < C_DIM / 2; k++) {
            u64 nvp = __ldg(nr + k);                  // native 64-bit pair
            u64 lpp = __ldg(lr + k);
            float2 nv = upk(nvp);
            float eh0 = ex2a(nv.x * KH);              // exp(0.5*n)
            float eh1 = ex2a(nv.y * KH);
            u64 ehp = pk(eh0, eh1);
            u64 ep  = mul2(ehp, ehp);                 // exp(n) = eh^2
            sep   = add2(sep, ep);
            dotp  = fma2(ep, lpp, dotp);
            selp  = add2(selp, ehp);
            dotlp = fma2(ehp, lpp, dotlp);
            n2p   = fma2(nvp, nvp, n2p);
        }
        float2 a;
        a = upk(sep);   float se   = a.x + a.y;
        a = upk(dotp);  float dot  = a.x + a.y;
        a = upk(selp);  float sel  = a.x + a.y;
        a = upk(dotlp); float dotl = a.x + a.y;

        int t = __ldg(targets + b);
        float nt  = __ldg((const float*)nr + t);
        float lpt = ((const float*)lr)[t];
        float eht = ex2a(nt * KH);
        float et  = eht * eht;
        se   = fmaf(EM1, et, se);   dot  = fmaf(EM1 * et,  lpt, dot);
        sel  = fmaf(EM1, eht, sel); dotl = fmaf(EM1 * eht, lpt, dotl);

        // one reciprocal serves both ratios
        float r = rcpa(se * sel);
        wacc  = fmaf(dot  * sel, r, wacc);            // sum_b dot/se
        wtacc = fmaf(dotl * se,  r, wtacc);           // sum_b dotl/sel
    }

    float2 nn = upk(n2p);
    float n2 = nn.x + nn.y;

    reduce3(wacc, wtacc, n2);
    __shared__ float sm[3][TPB / 32];
    int lane = threadIdx.x & 31, w = threadIdx.x >> 5;
    if (lane == 0) { sm[0][w] = wacc; sm[1][w] = wtacc; sm[2][w] = n2; }
    __syncthreads();
    if (w == 0) {
        float va = (lane < TPB / 32) ? sm[0][lane] : 0.f;
        float vb = (lane < TPB / 32) ? sm[1][lane] : 0.f;
        float vc = (lane < TPB / 32) ? sm[2][lane] : 0.f;
        #pragma unroll
        for (int o = 4; o; o >>= 1) {
            va += __shfl_xor_sync(0xffffffffu, va, o);
            vb += __shfl_xor_sync(0xffffffffu, vb, o);
            vc += __shfl_xor_sync(0xffffffffu, vc, o);
        }
        if (lane == 0) {
            atomicAdd(&g_Sw[s],  va);
            atomicAdd(&g_Swt[s], vb);
            atomicAdd(&g_Sn2[s], vc);
        }
    }
}

// ---- stage 3: finalize --------------------------------------------------------
__global__ void k_final(float* out, int B, int S) {
    if (threadIdx.x == 0 && blockIdx.x == 0) {
        double invB = 1.0 / (double)B;
        double wstar = (double)g_wstar * invB;
        double acc = 0.0;
        for (int s = 0; s < S; s++) {
            double w  = -(double)g_Sw[s]  * invB;
            double wt = -(double)g_Swt[s] * invB;
            double n2 = (double)g_Sn2[s];
            double sc1 = fmax(wstar - wt, 0.0);
            double sc2 = fmax(wstar - w + 0.05 * n2, 0.0);                    // MU*n2/2
            double sc3 = fmax(wt - 0.5 * wstar + 0.5 * w + 0.0125 * n2, 0.0); // MU*LAM*(1-LAM)/2
            acc += sc1 + sc2 + sc3;
        }
        out[0] = (float)(wstar + 0.05 * acc);    // RHO = 0.05
    }
}

// ---- launcher -------------------------------------------------------------------
extern "C" void kernel_launch(void* const* d_in, const int* in_sizes, int n_in,
                              void* d_out, int out_size) {
    const float* pred    = (const float*)d_in[0];
    const int*   targets = (const int*)d_in[1];
    const float* noise   = (const float*)d_in[2];
    float* out = (float*)d_out;

    int B = in_sizes[1];                       // 65536
    int S = in_sizes[2] / in_sizes[0];         // 128

    k_init<<<1, 256>>>();
    k_logsoftmax<<<(B + TPB - 1) / TPB, TPB>>>(pred, targets, B);
    int rpb = (B + BPS - 1) / BPS;
    k_main<<<S * BPS, TPB>>>(noise, targets, B, rpb);
    k_final<<<1, 32>>>(out, B, S);
}

// round 4
// speedup vs baseline: 1.0749x; 1.0749x over previous
#include <cuda_runtime.h>
#include <cstdint>

// ---------------------------------------------------------------------------
// starConvexLoss — R3: fused, DRAM-bound design
//   k_init : zero per-s accumulators + wstar
//   k_main : grid (B/256, S/16). Each thread owns ONE row b:
//              - computes logp row inline from pred (registers, no g_logp)
//              - loops 16 s values; per s reads only its 40B noise row
//              - exp(n) = exp(n/2)^2  -> one MUFU per element serves both softmaxes
//              - packed f32x2 FMA pipe math
//              - per-s block reduce (parity smem) + 3 atomicAdds
//   k_final: 1 block, thread-per-s, fp64 in parallel
// ---------------------------------------------------------------------------

#define C_DIM 10
#define TPB   256
#define SPG   16        // s-values per block

static __device__ float g_Sw[256];
static __device__ float g_Swt[256];
static __device__ float g_Sn2[256];
static __device__ float g_wstar;

// ---- fast math helpers ------------------------------------------------------
__device__ __forceinline__ float ex2a(float x) {
    float r; asm("ex2.approx.f32 %0, %1;" : "=f"(r) : "f"(x)); return r;
}
__device__ __forceinline__ float lg2a(float x) {
    float r; asm("lg2.approx.f32 %0, %1;" : "=f"(r) : "f"(x)); return r;
}
__device__ __forceinline__ float rcpa(float x) {
    float r; asm("rcp.approx.f32 %0, %1;" : "=f"(r) : "f"(x)); return r;
}

// ---- packed f32x2 (Blackwell) -------------------------------------------------
typedef unsigned long long u64;
__device__ __forceinline__ u64 fma2(u64 a, u64 b, u64 c) {
    u64 d; asm("fma.rn.f32x2 %0, %1, %2, %3;" : "=l"(d) : "l"(a), "l"(b), "l"(c)); return d;
}
__device__ __forceinline__ u64 add2(u64 a, u64 b) {
    u64 d; asm("add.rn.f32x2 %0, %1, %2;" : "=l"(d) : "l"(a), "l"(b)); return d;
}
__device__ __forceinline__ u64 mul2(u64 a, u64 b) {
    u64 d; asm("mul.rn.f32x2 %0, %1, %2;" : "=l"(d) : "l"(a), "l"(b)); return d;
}
__device__ __forceinline__ u64 pk(float x, float y) {
    u64 d; asm("mov.b64 %0, {%1, %2};" : "=l"(d) : "f"(x), "f"(y)); return d;
}
__device__ __forceinline__ float2 upk(u64 v) {
    float2 f; asm("mov.b64 {%0, %1}, %2;" : "=f"(f.x), "=f"(f.y) : "l"(v)); return f;
}

#define KH   0.7213475204444817f     // 0.5 * log2(e)
#define L2E  1.4426950408889634f
#define LN2  0.6931471805599453f
#define EM1  1.7182818284590452f     // e - 1

// ---- stage 0: zero accumulators -----------------------------------------------
__global__ void k_init() {
    int i = threadIdx.x;
    if (i < 256) { g_Sw[i] = 0.f; g_Swt[i] = 0.f; g_Sn2[i] = 0.f; }
    if (i == 0) g_wstar = 0.f;
}

// ---- stage 1: the fused main kernel --------------------------------------------
__global__ void __launch_bounds__(TPB) k_main(
    const float* __restrict__ pred, const int* __restrict__ targets,
    const float* __restrict__ noise, int B, int S) {

    int b_raw = blockIdx.x * TPB + threadIdx.x;
    float valid = (b_raw < B) ? 1.f : 0.f;
    int b = min(b_raw, B - 1);

    int s0   = blockIdx.y * SPG;
    int sEnd = min(s0 + SPG, S);

    // ---- inline log-softmax of this thread's pred row (registers only) ----
    float p[C_DIM];
    {
        const float2* pr = (const float2*)pred + (size_t)b * (C_DIM / 2);
        #pragma unroll
        for (int k = 0; k < C_DIM / 2; k++) {
            float2 v = __ldg(pr + k); p[2 * k] = v.x; p[2 * k + 1] = v.y;
        }
    }
    float m = p[0];
    #pragma unroll
    for (int c = 1; c < C_DIM; c++) m = fmaxf(m, p[c]);
    float sum = 0.f;
    #pragma unroll
    for (int c = 0; c < C_DIM; c++) sum += ex2a((p[c] - m) * L2E);
    float lse = fmaf(lg2a(sum), LN2, m);

    u64 lp[C_DIM / 2];
    #pragma unroll
    for (int k = 0; k < C_DIM / 2; k++)
        lp[k] = pk(p[2 * k] - lse, p[2 * k + 1] - lse);

    int t = __ldg(targets + b);
    float lpt = __ldg(pred + (size_t)b * C_DIM + t) - lse;   // logp[b,t]

    __shared__ float sm[2][3][TPB / 32];
    int lane = threadIdx.x & 31, w = threadIdx.x >> 5;

    // ---- wstar partial (only s-group 0 contributes) ----
    if (blockIdx.y == 0) {
        float wp = -lpt * valid;
        #pragma unroll
        for (int o = 16; o; o >>= 1) wp += __shfl_xor_sync(0xffffffffu, wp, o);
        if (lane == 0) atomicAdd(&g_wstar, wp);
    }

    // ---- s loop over noise, logp resident in registers ----
    const u64* nrow = (const u64*)noise + ((size_t)s0 * B + b) * (C_DIM / 2);
    const size_t sStride = (size_t)B * (C_DIM / 2);   // in u64 units

    u64 nv[C_DIM / 2];
    float ntc;
    #pragma unroll
    for (int k = 0; k < C_DIM / 2; k++) nv[k] = __ldg(nrow + k);
    ntc = __ldg((const float*)nrow + t);

    for (int s = s0; s < sEnd; s++) {
        // prefetch next s's noise row before the barrier
        u64 nn[C_DIM / 2]; float ntn = 0.f;
        const u64* nxt = nrow + sStride;
        if (s + 1 < sEnd) {
            #pragma unroll
            for (int k = 0; k < C_DIM / 2; k++) nn[k] = __ldg(nxt + k);
            ntn = __ldg((const float*)nxt + t);
        }

        u64 sep = 0ull, dotp = 0ull, selp = 0ull, dotlp = 0ull, n2p = 0ull;
        #pragma unroll
        for (int k = 0; k < C_DIM / 2; k++) {
            float2 a = upk(nv[k]);
            float eh0 = ex2a(a.x * KH);       // exp(0.5*n)
            float eh1 = ex2a(a.y * KH);
            u64 ehp = pk(eh0, eh1);
            u64 ep  = mul2(ehp, ehp);         // exp(n)
            sep   = add2(sep, ep);
            dotp  = fma2(ep, lp[k], dotp);
            selp  = add2(selp, ehp);
            dotlp = fma2(ehp, lp[k], dotlp);
            n2p   = fma2(nv[k], nv[k], n2p);
        }
        float2 v;
        v = upk(sep);   float se   = v.x + v.y;
        v = upk(dotp);  float dot  = v.x + v.y;
        v = upk(selp);  float sel  = v.x + v.y;
        v = upk(dotlp); float dotl = v.x + v.y;
        v = upk(n2p);   float n2r  = v.x + v.y;

        float eht = ex2a(ntc * KH);
        float et  = eht * eht;
        se   = fmaf(EM1, et, se);   dot  = fmaf(EM1 * et,  lpt, dot);
        sel  = fmaf(EM1, eht, sel); dotl = fmaf(EM1 * eht, lpt, dotl);

        float r = rcpa(se * sel);                  // one rcp serves both ratios
        float wr  = dot  * sel * r * valid;        // softCE contribution (w)
        float wtr = dotl * se  * r * valid;        // (wt)
        n2r *= valid;

        // rotate prefetch
        #pragma unroll
        for (int k = 0; k < C_DIM / 2; k++) nv[k] = nn[k];
        ntc = ntn;
        nrow = nxt;

        // block reduce (parity double-buffered smem: one barrier per s)
        #pragma unroll
        for (int o = 16; o; o >>= 1) {
            wr  += __shfl_xor_sync(0xffffffffu, wr,  o);
            wtr += __shfl_xor_sync(0xffffffffu, wtr, o);
            n2r += __shfl_xor_sync(0xffffffffu, n2r, o);
        }
        int par = s & 1;
        if (lane == 0) { sm[par][0][w] = wr; sm[par][1][w] = wtr; sm[par][2][w] = n2r; }
        __syncthreads();
        if (w == 0) {
            float va = (lane < TPB / 32) ? sm[par][0][lane] : 0.f;
            float vb = (lane < TPB / 32) ? sm[par][1][lane] : 0.f;
            float vc = (lane < TPB / 32) ? sm[par][2][lane] : 0.f;
            #pragma unroll
            for (int o = 4; o; o >>= 1) {
                va += __shfl_xor_sync(0xffffffffu, va, o);
                vb += __shfl_xor_sync(0xffffffffu, vb, o);
                vc += __shfl_xor_sync(0xffffffffu, vc, o);
            }
            if (lane == 0) {
                atomicAdd(&g_Sw[s],  va);
                atomicAdd(&g_Swt[s], vb);
                atomicAdd(&g_Sn2[s], vc);
            }
        }
    }
}

// ---- stage 2: finalize (thread-per-s, fp64 in parallel) --------------------------
__global__ void k_final(float* __restrict__ out, int B, int S) {
    int i = threadIdx.x;
    double invB = 1.0 / (double)B;
    double wstar = (double)g_wstar * invB;
    double acc = 0.0;
    if (i < S) {
        double w  = -(double)g_Sw[i]  * invB;
        double wt = -(double)g_Swt[i] * invB;
        double n2 = (double)g_Sn2[i];
        double sc1 = fmax(wstar - wt, 0.0);
        double sc2 = fmax(wstar - w + 0.05 * n2, 0.0);                    // MU*n2/2
        double sc3 = fmax(wt - 0.5 * wstar + 0.5 * w + 0.0125 * n2, 0.0); // MU*LAM*(1-LAM)/2
        acc = sc1 + sc2 + sc3;
    }
    // block reduce (256 threads, fp64)
    #pragma unroll
    for (int o = 16; o; o >>= 1) acc += __shfl_xor_sync(0xffffffffu, acc, o);
    __shared__ double sm[8];
    int lane = i & 31, w = i >> 5;
    if (lane == 0) sm[w] = acc;
    __syncthreads();
    if (w == 0) {
        double v = (lane < 8) ? sm[lane] : 0.0;
        #pragma unroll
        for (int o = 4; o; o >>= 1) v += __shfl_xor_sync(0xffffffffu, v, o);
        if (lane == 0) out[0] = (float)(wstar + 0.05 * v);   // RHO = 0.05
    }
}

// ---- launcher ---------------------------------------------------------------------
extern "C" void kernel_launch(void* const* d_in, const int* in_sizes, int n_in,
                              void* d_out, int out_size) {
    const float* pred    = (const float*)d_in[0];
    const int*   targets = (const int*)d_in[1];
    const float* noise   = (const float*)d_in[2];
    float* out = (float*)d_out;

    int B = in_sizes[1];                       // 65536
    int S = in_sizes[2] / in_sizes[0];         // 128

    k_init<<<1, 256>>>();
    dim3 grid((B + TPB - 1) / TPB, (S + SPG - 1) / SPG);
    k_main<<<grid, TPB>>>(pred, targets, noise, B, S);
    k_final<<<1, 256>>>(out, B, S);
}